// round 11
// baseline (speedup 1.0000x reference)
#include <cuda_runtime.h>
#include <cuda_fp16.h>
#include <cstdint>

#define NROWS 4096
#define KDIM  2048
#define MARGIN_F 0.3f

#define TM 128
#define TN 128
#define KC 64                        // f16 k-chunk: 128 bytes per row
#define NCHUNK (KDIM / KC)           // 32
#define NTHREADS 256                 // 8 warps, warp tile 64x32
#define NBT 32
#define NTILES (NBT * (NBT + 1) / 2) // 528 upper-tri tiles

#define A_BYTES (TM * KC * 2)        // 16384
#define B_BYTES (TN * KC * 2)        // 16384
#define STAGE_BYTES (A_BYTES + B_BYTES)   // 32768
#define NSTAGE 3
#define DYN_BYTES (NSTAGE * STAGE_BYTES + 1024)  // 99328

__device__ float  g_sq[NROWS];
__device__ int    g_ap[NROWS];   // d^2 bits (non-negative) -> int max/min valid
__device__ int    g_an[NROWS];
// fp16 copy, PRE-SWIZZLED: within each 128B k-segment, 16B unit u is stored
// at position (u ^ (row & 7)). Tiles start at row multiples of 128, so the
// pattern is tile-invariant and staging is a contiguous 128B copy per row.
__device__ __half g_xh[NROWS * KDIM];

static __device__ __forceinline__ uint32_t smem_u32(const void* p) {
    uint32_t a;
    asm("{ .reg .u64 t; cvta.to.shared.u64 t, %1; cvt.u32.u64 %0, t; }" : "=r"(a) : "l"(p));
    return a;
}
static __device__ __forceinline__ void mma_f16(float* d, const uint32_t* a, const uint32_t* b) {
    asm volatile(
        "mma.sync.aligned.m16n8k16.row.col.f32.f16.f16.f32 "
        "{%0,%1,%2,%3}, {%4,%5,%6,%7}, {%8,%9}, {%0,%1,%2,%3};"
        : "+f"(d[0]), "+f"(d[1]), "+f"(d[2]), "+f"(d[3])
        : "r"(a[0]), "r"(a[1]), "r"(a[2]), "r"(a[3]), "r"(b[0]), "r"(b[1]));
}
static __device__ __forceinline__ void ldsm4(uint32_t* r, uint32_t addr) {
    asm volatile("ldmatrix.sync.aligned.m8n8.x4.shared.b16 {%0,%1,%2,%3}, [%4];"
        : "=r"(r[0]), "=r"(r[1]), "=r"(r[2]), "=r"(r[3]) : "r"(addr));
}
static __device__ __forceinline__ void bulk128(uint32_t dst, const void* src, uint32_t mbar) {
    asm volatile(
        "cp.async.bulk.shared::cta.global.mbarrier::complete_tx::bytes [%0], [%1], %2, [%3];"
        :: "r"(dst), "l"(src), "r"(128u), "r"(mbar) : "memory");
}
#define MBAR_INIT(a, c) asm volatile("mbarrier.init.shared.b64 [%0], %1;" :: "r"(a), "r"((uint32_t)(c)) : "memory")
#define MBAR_EXPECT(a, n) asm volatile("mbarrier.arrive.expect_tx.shared.b64 _, [%0], %1;" :: "r"(a), "r"((uint32_t)(n)) : "memory")
#define MBAR_WAIT(mbar, parity) do {                                              \
    uint32_t _m = (mbar); uint32_t _p = (parity); uint32_t _done;                 \
    asm volatile("{\n\t.reg .pred p;\n\t"                                         \
        "mbarrier.try_wait.parity.acquire.cta.shared::cta.b64 p, [%1], %2;\n\t"   \
        "selp.b32 %0, 1, 0, p;\n\t}" : "=r"(_done) : "r"(_m), "r"(_p) : "memory");\
    if (!_done) {                                                                 \
        asm volatile("{\n\t.reg .pred P1;\n\t"                                    \
        "WL_%=:\n\t"                                                              \
        "mbarrier.try_wait.parity.acquire.cta.shared::cta.b64 P1, [%0], %1, 0x989680;\n\t" \
        "@P1 bra.uni WD_%=;\n\t"                                                  \
        "bra.uni WL_%=;\n\t"                                                      \
        "WD_%=:\n\t}" :: "r"(_m), "r"(_p) : "memory");                            \
    }                                                                             \
} while (0)

// ---------------------------------------------------------------------------
// Kernel 1: squared norms + init + PRE-SWIZZLED fp16 copy (4 rows / block,
// one 16B unit per thread per row -> 4-way MLP)
// ---------------------------------------------------------------------------
__global__ void __launch_bounds__(256) prep_kernel(const float* __restrict__ x) {
    int row0 = blockIdx.x * 4;
    int unit = threadIdx.x;                 // 0..255 (16B f16 units per row)
    int seg_base = (unit & ~7);             // unit group of this 128B segment
    int u3 = unit & 7;
    float s[4];
    #pragma unroll
    for (int r = 0; r < 4; r++) s[r] = 0.f;
    #pragma unroll
    for (int r = 0; r < 4; r++) {
        int row = row0 + r;
        const float4* src = reinterpret_cast<const float4*>(x + (size_t)row * KDIM) + unit * 2;
        float4 v0 = src[0];
        float4 v1 = src[1];
        s[r] += v0.x * v0.x + v0.y * v0.y + v0.z * v0.z + v0.w * v0.w
              + v1.x * v1.x + v1.y * v1.y + v1.z * v1.z + v1.w * v1.w;
        __half2 h0 = __floats2half2_rn(v0.x, v0.y), h1 = __floats2half2_rn(v0.z, v0.w);
        __half2 h2 = __floats2half2_rn(v1.x, v1.y), h3 = __floats2half2_rn(v1.z, v1.w);
        uint4 p;
        p.x = *reinterpret_cast<uint32_t*>(&h0); p.y = *reinterpret_cast<uint32_t*>(&h1);
        p.z = *reinterpret_cast<uint32_t*>(&h2); p.w = *reinterpret_cast<uint32_t*>(&h3);
        int dunit = seg_base | (u3 ^ (row & 7));   // swizzled unit within segment
        reinterpret_cast<uint4*>(g_xh + (size_t)row * KDIM)[dunit] = p;
    }
    __shared__ float red[32];
    #pragma unroll
    for (int o = 16; o; o >>= 1)
        #pragma unroll
        for (int r = 0; r < 4; r++) s[r] += __shfl_down_sync(0xffffffffu, s[r], o);
    if ((threadIdx.x & 31) == 0) {
        int w = threadIdx.x >> 5;
        #pragma unroll
        for (int r = 0; r < 4; r++) red[w * 4 + r] = s[r];
    }
    __syncthreads();
    if (threadIdx.x < 4) {
        float t = 0.f;
        #pragma unroll
        for (int w = 0; w < 8; w++) t += red[w * 4 + threadIdx.x];
        g_sq[row0 + threadIdx.x] = t;
        g_ap[row0 + threadIdx.x] = 0;
        g_an[row0 + threadIdx.x] = 0x7f800000;
    }
}

// ---------------------------------------------------------------------------
// Kernel 2: fp16 mma.sync Gram tile (128x128), 8 warps of 64x32, 3-stage
// cp.async.bulk (128B/row, 256 issues/chunk vs 2048) + mbarrier, 2 CTAs/SM.
// Flat triangular grid. Epilogue on d^2, row/col idempotent reductions.
// ---------------------------------------------------------------------------
__global__ void __launch_bounds__(NTHREADS, 2)
dist_kernel(const int* __restrict__ tg) {
    int tix = blockIdx.x;
    int bi = (int)((65.0f - sqrtf(4225.0f - 8.0f * (float)tix)) * 0.5f);
    while (bi * (65 - bi) / 2 > tix) bi--;
    while ((bi + 1) * (64 - bi) / 2 <= tix) bi++;
    int bj = bi + (tix - bi * (65 - bi) / 2);

    extern __shared__ char raw_dsm[];
    __shared__ unsigned long long s_mbar[NSTAGE];
    __shared__ int   s_ap_r[TM], s_an_r[TM];
    __shared__ int   s_ap_c[TN], s_an_c[TN];
    __shared__ float s_sqi[TM],  s_sqj[TN];
    __shared__ int   s_li[TM],   s_lj[TN];

    int tid = threadIdx.x, lid = tid & 31, wid = tid >> 5;
    int wm = wid >> 2, wn = wid & 3;       // 2 x 4 warp grid, warp tile 64x32
    int u = lid >> 2, v = lid & 3;
    int r8 = lid & 7, mq = lid >> 3;
    int mlow = mq & 1, mhigh = mq >> 1;

    uint32_t raw_base = smem_u32(raw_dsm);
    uint32_t sbase = (raw_base + 1023u) & ~1023u;
    uint32_t mb = smem_u32(&s_mbar[0]);

    const __half* Ab = g_xh + (size_t)(bi * TM) * KDIM;
    const __half* Bb = g_xh + (size_t)(bj * TN) * KDIM;

    if (tid == 0) {
        MBAR_INIT(mb, 1);
        MBAR_INIT(mb + 8, 1);
        MBAR_INIT(mb + 16, 1);
    }
    if (tid < TM) {
        s_ap_r[tid] = 0; s_an_r[tid] = 0x7f800000;
        s_sqi[tid] = g_sq[bi * TM + tid];
        s_li[tid]  = tg[bi * TM + tid];
        s_ap_c[tid] = 0; s_an_c[tid] = 0x7f800000;
        s_sqj[tid] = g_sq[bj * TN + tid];
        s_lj[tid]  = tg[bj * TN + tid];
    }
    __syncthreads();   // mbarrier init visible before any bulk targets them

    float acc[4][4][4];
    #pragma unroll
    for (int mt = 0; mt < 4; mt++)
        #pragma unroll
        for (int nt = 0; nt < 4; nt++)
            #pragma unroll
            for (int q = 0; q < 4; q++) acc[mt][nt][q] = 0.f;

    // ldmatrix lane bases (layout identical to R10: pre-swizzled in gmem)
    uint32_t a_lane = (uint32_t)((wm * 64 + mlow * 8 + r8) * 128);
    uint32_t b_lane = (uint32_t)A_BYTES + (uint32_t)((wn * 32 + mhigh * 8 + r8) * 128);
    uint32_t akx[4], bkx[4];
    #pragma unroll
    for (int ks = 0; ks < 4; ks++) {
        akx[ks] = (uint32_t)((ks * 32 + mhigh * 16) ^ (r8 * 16));
        bkx[ks] = (uint32_t)((ks * 32 + mlow  * 16) ^ (r8 * 16));
    }

    // per-thread bulk source/dst: one 128B row-chunk per thread per stage
    const __half* bulk_src = (tid < 128)
        ? (Ab + (size_t)tid * KDIM)
        : (Bb + (size_t)(tid - 128) * KDIM);
    uint32_t bulk_dst_off = (tid < 128) ? (uint32_t)(tid * 128)
                                        : (uint32_t)(A_BYTES + (tid - 128) * 128);

    #define STAGE_BULK(ic, s) do {                                             \
        if (tid == 0) MBAR_EXPECT(mb + (s) * 8, STAGE_BYTES);                  \
        bulk128(sbase + (uint32_t)(s) * STAGE_BYTES + bulk_dst_off,            \
                bulk_src + (ic) * KC, mb + (s) * 8);                           \
    } while (0)

    STAGE_BULK(0, 0);
    STAGE_BULK(1, 1);

    uint32_t phases = 0;   // parity bit per slot
    for (int ic = 0; ic < NCHUNK; ic++) {
        int s = ic % 3;
        __syncthreads();   // all warps finished reading slot (ic+2)%3 at ic-1

        if (ic + 2 < NCHUNK) STAGE_BULK(ic + 2, (ic + 2) % 3);

        MBAR_WAIT(mb + s * 8, (phases >> s) & 1);
        phases ^= (1u << s);

        uint32_t stg = sbase + (uint32_t)s * STAGE_BYTES;
        uint32_t a0 = stg + a_lane;
        uint32_t b0 = stg + b_lane;

        #pragma unroll
        for (int ks = 0; ks < 4; ks++) {
            uint32_t af[4][4], rb[2][4];
            #pragma unroll
            for (int mt = 0; mt < 4; mt++)
                ldsm4(af[mt], a0 + (uint32_t)(mt * 2048) + akx[ks]);
            #pragma unroll
            for (int ntp = 0; ntp < 2; ntp++)
                ldsm4(rb[ntp], b0 + (uint32_t)(ntp * 2048) + bkx[ks]);
            #pragma unroll
            for (int mt = 0; mt < 4; mt++) {
                #pragma unroll
                for (int ntp = 0; ntp < 2; ntp++) {
                    mma_f16(acc[mt][ntp * 2 + 0], af[mt], &rb[ntp][0]);
                    mma_f16(acc[mt][ntp * 2 + 1], af[mt], &rb[ntp][2]);
                }
            }
        }
    }

    // ---- epilogue: d^2, masked hardest pos/neg, idempotent reductions ----
    const float INF = __int_as_float(0x7f800000);
    float ap_r[8], an_r[8], ap_c[8], an_c[8];
    #pragma unroll
    for (int i = 0; i < 8; i++) { ap_r[i] = 0.f; an_r[i] = INF; ap_c[i] = 0.f; an_c[i] = INF; }

    #pragma unroll
    for (int mt = 0; mt < 4; mt++) {
        #pragma unroll
        for (int rh = 0; rh < 2; rh++) {
            int ml = wm * 64 + mt * 16 + u + rh * 8;
            float sqi = s_sqi[ml];
            int   li  = s_li[ml];
            int ri = mt * 2 + rh;
            float apv = ap_r[ri], anv = an_r[ri];
            #pragma unroll
            for (int nt = 0; nt < 4; nt++) {
                #pragma unroll
                for (int cb = 0; cb < 2; cb++) {
                    int nl = wn * 32 + nt * 8 + v * 2 + cb;
                    float d2 = fmaxf(fmaf(-2.f, acc[mt][nt][rh * 2 + cb],
                                          sqi + s_sqj[nl]), 0.f);
                    int ci = nt * 2 + cb;
                    if (li == s_lj[nl]) {
                        apv = fmaxf(apv, d2);
                        ap_c[ci] = fmaxf(ap_c[ci], d2);
                    } else {
                        anv = fminf(anv, d2);
                        an_c[ci] = fminf(an_c[ci], d2);
                    }
                }
            }
            ap_r[ri] = apv; an_r[ri] = anv;
        }
    }

    const unsigned FM = 0xffffffffu;
    #pragma unroll
    for (int i = 0; i < 8; i++) {          // reduce over v (4 col-lanes)
        float ap = ap_r[i], an = an_r[i];
        ap = fmaxf(ap, __shfl_xor_sync(FM, ap, 1));
        ap = fmaxf(ap, __shfl_xor_sync(FM, ap, 2));
        an = fminf(an, __shfl_xor_sync(FM, an, 1));
        an = fminf(an, __shfl_xor_sync(FM, an, 2));
        if (v == 0) {
            int ml = wm * 64 + (i >> 1) * 16 + u + (i & 1) * 8;
            atomicMax(&s_ap_r[ml], __float_as_int(ap));
            atomicMin(&s_an_r[ml], __float_as_int(an));
        }
    }
    #pragma unroll
    for (int i = 0; i < 8; i++) {          // reduce over u (8 row-lanes)
        float ap = ap_c[i], an = an_c[i];
        ap = fmaxf(ap, __shfl_xor_sync(FM, ap, 4));
        ap = fmaxf(ap, __shfl_xor_sync(FM, ap, 8));
        ap = fmaxf(ap, __shfl_xor_sync(FM, ap, 16));
        an = fminf(an, __shfl_xor_sync(FM, an, 4));
        an = fminf(an, __shfl_xor_sync(FM, an, 8));
        an = fminf(an, __shfl_xor_sync(FM, an, 16));
        if (u == 0) {
            int nl = wn * 32 + (i >> 1) * 8 + v * 2 + (i & 1);
            atomicMax(&s_ap_c[nl], __float_as_int(ap));
            atomicMin(&s_an_c[nl], __float_as_int(an));
        }
    }
    __syncthreads();

    if (tid < TM) {
        atomicMax(&g_ap[bi * TM + tid], s_ap_r[tid]);
        atomicMin(&g_an[bi * TM + tid], s_an_r[tid]);
        atomicMax(&g_ap[bj * TN + tid], s_ap_c[tid]);
        atomicMin(&g_an[bj * TN + tid], s_an_c[tid]);
    }
}

// ---------------------------------------------------------------------------
// Kernel 3: loss = mean(relu(margin + sqrt(ap2) - sqrt(an2)))
// ---------------------------------------------------------------------------
__global__ void __launch_bounds__(1024) loss_kernel(float* __restrict__ out) {
    float s = 0.f;
    for (int i = threadIdx.x; i < NROWS; i += 1024) {
        float ap = sqrtf(fmaxf(__int_as_float(g_ap[i]), 1e-12f));
        float an = sqrtf(fmaxf(__int_as_float(g_an[i]), 1e-12f));
        s += fmaxf(MARGIN_F + ap - an, 0.f);
    }
    __shared__ float red[32];
    #pragma unroll
    for (int o = 16; o; o >>= 1) s += __shfl_down_sync(0xffffffffu, s, o);
    if ((threadIdx.x & 31) == 0) red[threadIdx.x >> 5] = s;
    __syncthreads();
    if (threadIdx.x < 32) {
        float t = red[threadIdx.x];
        #pragma unroll
        for (int o = 16; o; o >>= 1) t += __shfl_down_sync(0xffffffffu, t, o);
        if (threadIdx.x == 0) out[0] = t / (float)NROWS;
    }
}

extern "C" void kernel_launch(void* const* d_in, const int* in_sizes, int n_in,
                              void* d_out, int out_size) {
    const float* x  = (const float*)d_in[0];
    const int*   tg = (const int*)d_in[1];
    float* out = (float*)d_out;

    cudaFuncSetAttribute(dist_kernel, cudaFuncAttributeMaxDynamicSharedMemorySize, DYN_BYTES);

    prep_kernel<<<NROWS / 4, 256>>>(x);
    dist_kernel<<<NTILES, NTHREADS, DYN_BYTES>>>(tg);
    loss_kernel<<<1, 1024>>>(out);
}

// round 12
// speedup vs baseline: 1.3185x; 1.3185x over previous
#include <cuda_runtime.h>
#include <cuda_fp16.h>
#include <cstdint>

#define NROWS 4096
#define KDIM  2048
#define MARGIN_F 0.3f

#define TM 128
#define TN 128
#define KC 64                        // f16 k-chunk: 128 bytes per row
#define NCHUNK (KDIM / KC)           // 32
#define NTHREADS 256                 // 8 warps, warp tile 64x32
#define NBT 32
#define NTILES (NBT * (NBT + 1) / 2) // 528 upper-tri tiles

#define A_BYTES (TM * KC * 2)        // 16384
#define B_BYTES (TN * KC * 2)        // 16384
#define STAGE_BYTES (A_BYTES + B_BYTES)   // 32768
#define NSTAGE 3
#define DYN_BYTES (NSTAGE * STAGE_BYTES + 1024)  // 99328

__device__ float  g_sq[NROWS];
__device__ int    g_ap[NROWS];   // d^2 bits (non-negative) -> int max/min valid
__device__ int    g_an[NROWS];
// fp16 copy, PRE-SWIZZLED: within each 128B k-segment, 16B unit u is stored
// at position (u ^ (row & 7)). Tiles start at row multiples of 8, so the
// pattern is tile-invariant; staging is a plain linear copy and ldmatrix
// reads with the XOR pattern hit conflict-free banks.
__device__ __half g_xh[NROWS * KDIM];

static __device__ __forceinline__ uint32_t smem_u32(const void* p) {
    uint32_t a;
    asm("{ .reg .u64 t; cvta.to.shared.u64 t, %1; cvt.u32.u64 %0, t; }" : "=r"(a) : "l"(p));
    return a;
}
static __device__ __forceinline__ void cp16(uint32_t s, const void* g) {
    asm volatile("cp.async.cg.shared.global [%0], [%1], 16;" :: "r"(s), "l"(g));
}
#define CP_COMMIT() asm volatile("cp.async.commit_group;" ::: "memory")
#define CP_WAIT1()  asm volatile("cp.async.wait_group 1;" ::: "memory")

static __device__ __forceinline__ void mma_f16(float* d, const uint32_t* a, const uint32_t* b) {
    asm volatile(
        "mma.sync.aligned.m16n8k16.row.col.f32.f16.f16.f32 "
        "{%0,%1,%2,%3}, {%4,%5,%6,%7}, {%8,%9}, {%0,%1,%2,%3};"
        : "+f"(d[0]), "+f"(d[1]), "+f"(d[2]), "+f"(d[3])
        : "r"(a[0]), "r"(a[1]), "r"(a[2]), "r"(a[3]), "r"(b[0]), "r"(b[1]));
}
static __device__ __forceinline__ void ldsm4(uint32_t* r, uint32_t addr) {
    asm volatile("ldmatrix.sync.aligned.m8n8.x4.shared.b16 {%0,%1,%2,%3}, [%4];"
        : "=r"(r[0]), "=r"(r[1]), "=r"(r[2]), "=r"(r[3]) : "r"(addr));
}

// ---------------------------------------------------------------------------
// Kernel 1: squared norms + init + PRE-SWIZZLED fp16 copy (4 rows / block,
// one 16B unit per thread per row -> 4-way MLP)
// ---------------------------------------------------------------------------
__global__ void __launch_bounds__(256) prep_kernel(const float* __restrict__ x) {
    int row0 = blockIdx.x * 4;
    int unit = threadIdx.x;                 // 0..255 (16B f16 units per row)
    int seg_base = (unit & ~7);             // unit group of this 128B segment
    int u3 = unit & 7;
    float s[4];
    #pragma unroll
    for (int r = 0; r < 4; r++) s[r] = 0.f;
    #pragma unroll
    for (int r = 0; r < 4; r++) {
        int row = row0 + r;
        const float4* src = reinterpret_cast<const float4*>(x + (size_t)row * KDIM) + unit * 2;
        float4 v0 = src[0];
        float4 v1 = src[1];
        s[r] += v0.x * v0.x + v0.y * v0.y + v0.z * v0.z + v0.w * v0.w
              + v1.x * v1.x + v1.y * v1.y + v1.z * v1.z + v1.w * v1.w;
        __half2 h0 = __floats2half2_rn(v0.x, v0.y), h1 = __floats2half2_rn(v0.z, v0.w);
        __half2 h2 = __floats2half2_rn(v1.x, v1.y), h3 = __floats2half2_rn(v1.z, v1.w);
        uint4 p;
        p.x = *reinterpret_cast<uint32_t*>(&h0); p.y = *reinterpret_cast<uint32_t*>(&h1);
        p.z = *reinterpret_cast<uint32_t*>(&h2); p.w = *reinterpret_cast<uint32_t*>(&h3);
        int dunit = seg_base | (u3 ^ (row & 7));   // swizzled unit within segment
        reinterpret_cast<uint4*>(g_xh + (size_t)row * KDIM)[dunit] = p;
    }
    __shared__ float red[32];
    #pragma unroll
    for (int o = 16; o; o >>= 1)
        #pragma unroll
        for (int r = 0; r < 4; r++) s[r] += __shfl_down_sync(0xffffffffu, s[r], o);
    if ((threadIdx.x & 31) == 0) {
        int w = threadIdx.x >> 5;
        #pragma unroll
        for (int r = 0; r < 4; r++) red[w * 4 + r] = s[r];
    }
    __syncthreads();
    if (threadIdx.x < 4) {
        float t = 0.f;
        #pragma unroll
        for (int w = 0; w < 8; w++) t += red[w * 4 + threadIdx.x];
        g_sq[row0 + threadIdx.x] = t;
        g_ap[row0 + threadIdx.x] = 0;
        g_an[row0 + threadIdx.x] = 0x7f800000;
    }
}

// ---------------------------------------------------------------------------
// Kernel 2: fp16 mma.sync Gram tile (128x128), 8 warps of 64x32, 3-stage
// cp.async.cg (linear copy, swizzle pre-baked in gmem), 2 CTAs/SM.
// Flat triangular grid. Epilogue on d^2, row/col idempotent reductions.
// ---------------------------------------------------------------------------
__global__ void __launch_bounds__(NTHREADS, 2)
dist_kernel(const int* __restrict__ tg) {
    // decode flat tile index -> (bi, bj), bj >= bi
    int tix = blockIdx.x;
    int bi = (int)((65.0f - sqrtf(4225.0f - 8.0f * (float)tix)) * 0.5f);
    while (bi * (65 - bi) / 2 > tix) bi--;
    while ((bi + 1) * (64 - bi) / 2 <= tix) bi++;
    int bj = bi + (tix - bi * (65 - bi) / 2);

    extern __shared__ char raw_dsm[];
    __shared__ int   s_ap_r[TM], s_an_r[TM];
    __shared__ int   s_ap_c[TN], s_an_c[TN];
    __shared__ float s_sqi[TM],  s_sqj[TN];
    __shared__ int   s_li[TM],   s_lj[TN];

    int tid = threadIdx.x, lid = tid & 31, wid = tid >> 5;
    int wm = wid >> 2, wn = wid & 3;       // 2 x 4 warp grid, warp tile 64x32
    int u = lid >> 2, v = lid & 3;
    int r8 = lid & 7, mq = lid >> 3;       // ldmatrix lane decomposition
    int mlow = mq & 1, mhigh = mq >> 1;

    uint32_t raw_base = smem_u32(raw_dsm);
    uint32_t sbase = (raw_base + 1023u) & ~1023u;

    const __half* Ab = g_xh + (size_t)(bi * TM) * KDIM;
    const __half* Bb = g_xh + (size_t)(bj * TN) * KDIM;

    if (tid < TM) {
        s_ap_r[tid] = 0; s_an_r[tid] = 0x7f800000;
        s_sqi[tid] = g_sq[bi * TM + tid];
        s_li[tid]  = tg[bi * TM + tid];
        s_ap_c[tid] = 0; s_an_c[tid] = 0x7f800000;
        s_sqj[tid] = g_sq[bj * TN + tid];
        s_lj[tid]  = tg[bj * TN + tid];
    }

    float acc[4][4][4];
    #pragma unroll
    for (int mt = 0; mt < 4; mt++)
        #pragma unroll
        for (int nt = 0; nt < 4; nt++)
            #pragma unroll
            for (int q = 0; q < 4; q++) acc[mt][nt][q] = 0.f;

    // ldmatrix lane bases: 128B rows (64 f16), 16B-unit XOR pattern baked
    // into gmem by prep; smem image identical to R10's staged layout.
    uint32_t a_lane = (uint32_t)((wm * 64 + mlow * 8 + r8) * 128);
    uint32_t b_lane = (uint32_t)A_BYTES + (uint32_t)((wn * 32 + mhigh * 8 + r8) * 128);
    uint32_t akx[4], bkx[4];
    #pragma unroll
    for (int ks = 0; ks < 4; ks++) {
        akx[ks] = (uint32_t)((ks * 32 + mhigh * 16) ^ (r8 * 16));
        bkx[ks] = (uint32_t)((ks * 32 + mlow  * 16) ^ (r8 * 16));
    }

    // staging: LINEAR copy (swizzle pre-baked): dst = base + idx*16
    #define STAGE(ic, s) do {                                                  \
        uint32_t b0_ = sbase + (uint32_t)(s) * STAGE_BYTES;                    \
        const __half* Ak_ = Ab + (ic) * KC;                                    \
        const __half* Bk_ = Bb + (ic) * KC;                                    \
        _Pragma("unroll")                                                      \
        for (int t = 0; t < 4; t++) {                                          \
            int idx = tid + t * NTHREADS; int r = idx >> 3, c4 = idx & 7;      \
            cp16(b0_ + (uint32_t)idx * 16, Ak_ + (size_t)r * KDIM + c4 * 8);   \
        }                                                                      \
        _Pragma("unroll")                                                      \
        for (int t = 0; t < 4; t++) {                                          \
            int idx = tid + t * NTHREADS; int r = idx >> 3, c4 = idx & 7;      \
            cp16(b0_ + A_BYTES + (uint32_t)idx * 16,                           \
                 Bk_ + (size_t)r * KDIM + c4 * 8);                             \
        }                                                                      \
    } while (0)

    STAGE(0, 0); CP_COMMIT();
    STAGE(1, 1); CP_COMMIT();

    int snext = 2;
    for (int ic = 0; ic < NCHUNK; ic++) {
        CP_WAIT1();
        __syncthreads();   // stage ic ready; slot snext was fully read in ic-1

        if (ic + 2 < NCHUNK) { STAGE(ic + 2, snext); }
        CP_COMMIT();

        int s = snext + 1; if (s >= NSTAGE) s -= NSTAGE;   // = ic % 3
        snext = s;

        uint32_t stg = sbase + (uint32_t)s * STAGE_BYTES;
        uint32_t a0 = stg + a_lane;
        uint32_t b0 = stg + b_lane;

        #pragma unroll
        for (int ks = 0; ks < 4; ks++) {
            uint32_t af[4][4], rb[2][4];
            #pragma unroll
            for (int mt = 0; mt < 4; mt++)
                ldsm4(af[mt], a0 + (uint32_t)(mt * 2048) + akx[ks]);
            #pragma unroll
            for (int ntp = 0; ntp < 2; ntp++)
                ldsm4(rb[ntp], b0 + (uint32_t)(ntp * 2048) + bkx[ks]);
            #pragma unroll
            for (int mt = 0; mt < 4; mt++) {
                #pragma unroll
                for (int ntp = 0; ntp < 2; ntp++) {
                    mma_f16(acc[mt][ntp * 2 + 0], af[mt], &rb[ntp][0]);
                    mma_f16(acc[mt][ntp * 2 + 1], af[mt], &rb[ntp][2]);
                }
            }
        }
    }

    // ---- epilogue: d^2, masked hardest pos/neg, idempotent reductions ----
    const float INF = __int_as_float(0x7f800000);
    float ap_r[8], an_r[8], ap_c[8], an_c[8];
    #pragma unroll
    for (int i = 0; i < 8; i++) { ap_r[i] = 0.f; an_r[i] = INF; ap_c[i] = 0.f; an_c[i] = INF; }

    #pragma unroll
    for (int mt = 0; mt < 4; mt++) {
        #pragma unroll
        for (int rh = 0; rh < 2; rh++) {
            int ml = wm * 64 + mt * 16 + u + rh * 8;
            float sqi = s_sqi[ml];
            int   li  = s_li[ml];
            int ri = mt * 2 + rh;
            float apv = ap_r[ri], anv = an_r[ri];
            #pragma unroll
            for (int nt = 0; nt < 4; nt++) {
                #pragma unroll
                for (int cb = 0; cb < 2; cb++) {
                    int nl = wn * 32 + nt * 8 + v * 2 + cb;
                    float d2 = fmaxf(fmaf(-2.f, acc[mt][nt][rh * 2 + cb],
                                          sqi + s_sqj[nl]), 0.f);
                    int ci = nt * 2 + cb;
                    if (li == s_lj[nl]) {
                        apv = fmaxf(apv, d2);
                        ap_c[ci] = fmaxf(ap_c[ci], d2);
                    } else {
                        anv = fminf(anv, d2);
                        an_c[ci] = fminf(an_c[ci], d2);
                    }
                }
            }
            ap_r[ri] = apv; an_r[ri] = anv;
        }
    }

    const unsigned FM = 0xffffffffu;
    #pragma unroll
    for (int i = 0; i < 8; i++) {          // reduce over v (4 col-lanes)
        float ap = ap_r[i], an = an_r[i];
        ap = fmaxf(ap, __shfl_xor_sync(FM, ap, 1));
        ap = fmaxf(ap, __shfl_xor_sync(FM, ap, 2));
        an = fminf(an, __shfl_xor_sync(FM, an, 1));
        an = fminf(an, __shfl_xor_sync(FM, an, 2));
        if (v == 0) {
            int ml = wm * 64 + (i >> 1) * 16 + u + (i & 1) * 8;
            atomicMax(&s_ap_r[ml], __float_as_int(ap));
            atomicMin(&s_an_r[ml], __float_as_int(an));
        }
    }
    #pragma unroll
    for (int i = 0; i < 8; i++) {          // reduce over u (8 row-lanes)
        float ap = ap_c[i], an = an_c[i];
        ap = fmaxf(ap, __shfl_xor_sync(FM, ap, 4));
        ap = fmaxf(ap, __shfl_xor_sync(FM, ap, 8));
        ap = fmaxf(ap, __shfl_xor_sync(FM, ap, 16));
        an = fminf(an, __shfl_xor_sync(FM, an, 4));
        an = fminf(an, __shfl_xor_sync(FM, an, 8));
        an = fminf(an, __shfl_xor_sync(FM, an, 16));
        if (u == 0) {
            int nl = wn * 32 + (i >> 1) * 8 + v * 2 + (i & 1);
            atomicMax(&s_ap_c[nl], __float_as_int(ap));
            atomicMin(&s_an_c[nl], __float_as_int(an));
        }
    }
    __syncthreads();

    if (tid < TM) {
        atomicMax(&g_ap[bi * TM + tid], s_ap_r[tid]);
        atomicMin(&g_an[bi * TM + tid], s_an_r[tid]);
        atomicMax(&g_ap[bj * TN + tid], s_ap_c[tid]);
        atomicMin(&g_an[bj * TN + tid], s_an_c[tid]);
    }
}

// ---------------------------------------------------------------------------
// Kernel 3: loss = mean(relu(margin + sqrt(ap2) - sqrt(an2)))
// ---------------------------------------------------------------------------
__global__ void __launch_bounds__(1024) loss_kernel(float* __restrict__ out) {
    float s = 0.f;
    for (int i = threadIdx.x; i < NROWS; i += 1024) {
        float ap = sqrtf(fmaxf(__int_as_float(g_ap[i]), 1e-12f));
        float an = sqrtf(fmaxf(__int_as_float(g_an[i]), 1e-12f));
        s += fmaxf(MARGIN_F + ap - an, 0.f);
    }
    __shared__ float red[32];
    #pragma unroll
    for (int o = 16; o; o >>= 1) s += __shfl_down_sync(0xffffffffu, s, o);
    if ((threadIdx.x & 31) == 0) red[threadIdx.x >> 5] = s;
    __syncthreads();
    if (threadIdx.x < 32) {
        float t = red[threadIdx.x];
        #pragma unroll
        for (int o = 16; o; o >>= 1) t += __shfl_down_sync(0xffffffffu, t, o);
        if (threadIdx.x == 0) out[0] = t / (float)NROWS;
    }
}

extern "C" void kernel_launch(void* const* d_in, const int* in_sizes, int n_in,
                              void* d_out, int out_size) {
    const float* x  = (const float*)d_in[0];
    const int*   tg = (const int*)d_in[1];
    float* out = (float*)d_out;

    cudaFuncSetAttribute(dist_kernel, cudaFuncAttributeMaxDynamicSharedMemorySize, DYN_BYTES);

    prep_kernel<<<NROWS / 4, 256>>>(x);
    dist_kernel<<<NTILES, NTHREADS, DYN_BYTES>>>(tg);
    loss_kernel<<<1, 1024>>>(out);
}